// round 15
// baseline (speedup 1.0000x reference)
#include <cuda_runtime.h>
#include <cuda_fp16.h>
#include <cstdint>

#define N_TOK   131072
#define DIM     64
#define NE      512
#define TILE_M  256
#define N_TILES 512
#define NTHR    512
#define NCTA    296
#define TAU     1.3e-4f

#define OUT_Q     0ull
#define OUT_DIFF  8388608ull
#define OUT_IND   8388609ull
#define OUT_EMB   8519681ull
#define OUT_CS    8552449ull
#define OUT_AVG   8552961ull

// smem layout (byte offsets) — 104 KB/CTA so 2 CTAs fit per SM
#define SB_HI   0               // codebook: f16(-2E) hi, 512 x 128B, SW128 (64KB)
#define SA      65536           // A tile: 256 x 128B f16(x) (32KB)
#define SSQ     98304           // ||E||^2 exact [512]
#define SSQO    100352          // ||E||^2 + 0.5 [512 + 16 pad]
#define SIND    102464          // argmin [256]
#define SHIST   103488          // [512]
#define SLIST   105536          // flagged tokens [256]
#define SCNT    106560
#define SMEM_TOTAL 106576

#define SWZ(o) ((o) ^ (((o) >> 3) & 0x70))

// scratch: zero at start (static init); finalizer resets counters each launch.
// g_embedT is rewritten identically by every CTA each launch (value-race-free).
__device__ float        g_embedT[NE * DIM];      // [e][d] exact fp32 codebook
__device__ float        g_embed_sum[NE * DIM];   // [e][d]
__device__ unsigned int g_hist[NE];
__device__ double       g_diff;
__device__ unsigned int g_done;

static __device__ __forceinline__ uint32_t smem_u32(const void* p) {
    uint32_t a;
    asm("{ .reg .u64 t; cvta.to.shared.u64 t, %1; cvt.u32.u64 %0, t; }" : "=r"(a) : "l"(p));
    return a;
}
static __device__ __forceinline__ uint32_t h2u(__half2 v) {
    uint32_t u; memcpy(&u, &v, 4); return u;
}
static __device__ __forceinline__ void mma16816(float* c, const uint32_t* a,
                                                const uint32_t* b) {
    asm volatile(
        "mma.sync.aligned.m16n8k16.row.col.f32.f16.f16.f32 "
        "{%0,%1,%2,%3}, {%4,%5,%6,%7}, {%8,%9}, {%0,%1,%2,%3};"
        : "+f"(c[0]), "+f"(c[1]), "+f"(c[2]), "+f"(c[3])
        : "r"(a[0]), "r"(a[1]), "r"(a[2]), "r"(a[3]), "r"(b[0]), "r"(b[1]));
}
static __device__ __forceinline__ void ldsm4(uint32_t* r, uint32_t addr) {
    asm volatile("ldmatrix.sync.aligned.m8n8.x4.shared.b16 {%0,%1,%2,%3}, [%4];"
                 : "=r"(r[0]), "=r"(r[1]), "=r"(r[2]), "=r"(r[3]) : "r"(addr));
}
static __device__ __forceinline__ void top2(uint32_t& k1, uint32_t& k2, uint32_t k) {
    uint32_t mx = k > k1 ? k : k1;
    k1 = k < k1 ? k : k1;
    k2 = mx < k2 ? mx : k2;
}

__global__ __launch_bounds__(NTHR, 2)
void vq_main(const float* __restrict__ x, const float* __restrict__ embed,
             const float* __restrict__ cs_in, const float* __restrict__ ea_in,
             float* __restrict__ out) {
    extern __shared__ char smc[];
    float*        ssq   = (float*)(smc + SSQ);
    float*        ssqo  = (float*)(smc + SSQO);
    int*          sind  = (int*)(smc + SIND);
    unsigned int* shist = (unsigned int*)(smc + SHIST);
    int*          slist = (int*)(smc + SLIST);
    int*          scnt  = (int*)(smc + SCNT);
    __shared__ unsigned int s_rank;

    const int tid  = threadIdx.x;
    const int lane = tid & 31;
    const int w    = tid >> 5;
    const uint32_t sbase = smem_u32(smc);

    // ---- prologue: f16 hi of (-2E); exact fp32 transposed codebook; ||E||^2 ----
    if (tid < NE) shist[tid] = 0u;
    for (int idx = tid; idx < DIM * NE; idx += NTHR) {
        int d = idx >> 9;                 // embed is [d][e], e fastest -> coalesced
        int e = idx & (NE - 1);
        float v = embed[idx];
        g_embedT[e * DIM + d] = v;        // identical values from all CTAs: benign
        __half h = __float2half_rn(-2.0f * v);
        uint32_t so = SWZ((uint32_t)(e * 128 + d * 2));
        *(__half*)(smc + SB_HI + so) = h;
    }
    if (tid < NE) {
        float s = 0.0f;
#pragma unroll
        for (int d = 0; d < DIM; d++) {
            float v = embed[d * NE + tid];
            s = __fmaf_rn(v, v, s);
        }
        ssq[tid]  = s;
        ssqo[tid] = s + 0.5f;
    }
    if (tid < 16) ssqo[NE + tid] = 0.0f;   // pad for seed prefetch
    __syncthreads();

    const int mat  = lane >> 3;
    const int mrow = lane & 7;
    const int q    = lane >> 2;
    const int cq   = lane & 3;
    const int tok2 = lane >> 4;
    const int fidx = lane & 15;

    float diff_acc = 0.0f;

    for (int tile = blockIdx.x; tile < N_TILES; tile += NCTA) {
        // ---- phase 1: coalesced f16 convert ----
        if (tid == 0) *scnt = 0;
#pragma unroll
        for (int j = 0; j < 8; j++) {
            const int t = w * 16 + j * 2 + tok2;
            float4 v = *(const float4*)(x + ((size_t)tile * TILE_M + t) * DIM
                                        + fidx * 4);
            uint32_t pa = h2u(__float22half2_rn(make_float2(v.x, v.y)));
            uint32_t pb = h2u(__float22half2_rn(make_float2(v.z, v.w)));
            uint32_t so = SWZ((uint32_t)(t * 128 + fidx * 8));
            *(uint2*)(smc + SA + so) = make_uint2(pa, pb);
        }
        __syncthreads();

        // ---- phase 2: warp w owns tokens [w*16, w*16+16) ----
        uint32_t AH[4][4];
#pragma unroll
        for (int ks = 0; ks < 4; ks++) {
            int trow = w * 16 + (mat & 1) * 8 + mrow;
            uint32_t off = SWZ((uint32_t)(trow * 128 + ks * 32 + (mat >> 1) * 16));
            ldsm4(AH[ks], sbase + SA + off);
        }
        uint32_t bAddr0, bAddr1, bAddr2, bAddr3;
        {
            const uint32_t bb = (uint32_t)(((mat >> 1) * 8 + mrow) * 128 + (mat & 1) * 16);
            bAddr0 = sbase + SB_HI + SWZ(bb);
            bAddr1 = sbase + SB_HI + SWZ(bb + 32);
            bAddr2 = sbase + SB_HI + SWZ(bb + 64);
            bAddr3 = sbase + SB_HI + SWZ(bb + 96);
        }
        uint32_t k1a[2] = {~0u, ~0u}, k2a[2] = {~0u, ~0u};
        uint32_t k1b[2] = {~0u, ~0u}, k2b[2] = {~0u, ~0u};

        float2 sqa = *(const float2*)(ssqo + 2 * cq);
        float2 sqb = *(const float2*)(ssqo + 8 + 2 * cq);

#pragma unroll 1
        for (int nb = 0; nb < NE; nb += 16) {
            uint32_t BH[4][4];
            ldsm4(BH[0], bAddr0); bAddr0 += 2048;
            ldsm4(BH[1], bAddr1); bAddr1 += 2048;
            ldsm4(BH[2], bAddr2); bAddr2 += 2048;
            ldsm4(BH[3], bAddr3); bAddr3 += 2048;
            float acc[2][4];
            acc[0][0] = sqa.x; acc[0][1] = sqa.y; acc[0][2] = sqa.x; acc[0][3] = sqa.y;
            acc[1][0] = sqb.x; acc[1][1] = sqb.y; acc[1][2] = sqb.x; acc[1][3] = sqb.y;
            sqa = *(const float2*)(ssqo + (nb + 16) + 2 * cq);
            sqb = *(const float2*)(ssqo + (nb + 24) + 2 * cq);
#pragma unroll
            for (int ks = 0; ks < 4; ks++) {
                mma16816(acc[0], AH[ks], &BH[ks][0]);
                mma16816(acc[1], AH[ks], &BH[ks][2]);
            }
            const uint32_t c0 = (uint32_t)(nb + 2 * cq);
#pragma unroll
            for (int hr = 0; hr < 2; hr++) {
                top2(k1a[hr], k2a[hr], (__float_as_uint(acc[0][hr * 2 + 0]) & 0xFFFFFE00u) | c0);
                top2(k1b[hr], k2b[hr], (__float_as_uint(acc[1][hr * 2 + 0]) & 0xFFFFFE00u) | (c0 + 8));
                top2(k1a[hr], k2a[hr], (__float_as_uint(acc[0][hr * 2 + 1]) & 0xFFFFFE00u) | (c0 + 1));
                top2(k1b[hr], k2b[hr], (__float_as_uint(acc[1][hr * 2 + 1]) & 0xFFFFFE00u) | (c0 + 9));
            }
        }
#pragma unroll
        for (int r = 0; r < 2; r++) {
            uint32_t mx = k1a[r] > k1b[r] ? k1a[r] : k1b[r];
            uint32_t b1 = k1a[r] < k1b[r] ? k1a[r] : k1b[r];
            uint32_t b2 = k2a[r] < k2b[r] ? k2a[r] : k2b[r];
            b2 = mx < b2 ? mx : b2;
#pragma unroll
            for (int off = 1; off < 4; off <<= 1) {
                uint32_t o1 = __shfl_xor_sync(0xffffffffu, b1, off);
                uint32_t o2 = __shfl_xor_sync(0xffffffffu, b2, off);
                uint32_t m2 = b1 > o1 ? b1 : o1;
                b1 = b1 < o1 ? b1 : o1;
                b2 = b2 < o2 ? b2 : o2;
                b2 = m2 < b2 ? m2 : b2;
            }
            if (cq == 0) {
                int t = w * 16 + q + r * 8;
                sind[t] = (int)(b1 & 0x1FFu);
                float f1 = __uint_as_float(b1 & 0xFFFFFE00u);
                float f2 = __uint_as_float(b2 & 0xFFFFFE00u);
                if (f2 - f1 < TAU) {
                    int idx = atomicAdd(scnt, 1);
                    slist[idx] = t;
                }
            }
        }
        __syncthreads();

        // ---- phase 2b: exact fp32 rescore ----
        const int cnt = *scnt;
        for (int i = w; i < cnt; i += 16) {
            const int t = slist[i];
            const float* xp = x + ((size_t)tile * TILE_M + t) * DIM;
            float pf = __fmaf_rn(xp[lane], xp[lane], xp[lane + 32] * xp[lane + 32]);
#pragma unroll
            for (int off = 16; off; off >>= 1)
                pf += __shfl_xor_sync(0xffffffffu, pf, off);
            const float sumf = pf;
            float bb = 3.4028235e38f;
            int   be = 0;
#pragma unroll 1
            for (int g = 0; g < 16; g++) {
                int e = g * 32 + lane;
                float d0 = 0.f, d1 = 0.f, d2 = 0.f, d3 = 0.f;
#pragma unroll
                for (int d = 0; d < DIM; d += 4) {
                    d0 = __fmaf_rn(xp[d],     embed[d * NE + e],       d0);
                    d1 = __fmaf_rn(xp[d + 1], embed[(d + 1) * NE + e], d1);
                    d2 = __fmaf_rn(xp[d + 2], embed[(d + 2) * NE + e], d2);
                    d3 = __fmaf_rn(xp[d + 3], embed[(d + 3) * NE + e], d3);
                }
                float dot = (d0 + d1) + (d2 + d3);
                float dist = __fmaf_rn(-2.0f, dot, sumf) + ssq[e];
                if (dist < bb) { bb = dist; be = e; }
            }
#pragma unroll
            for (int off = 16; off; off >>= 1) {
                float ob = __shfl_xor_sync(0xffffffffu, bb, off);
                int   oe = __shfl_xor_sync(0xffffffffu, be, off);
                if (ob < bb || (ob == bb && oe < be)) { bb = ob; be = oe; }
            }
            if (lane == 0) sind[t] = be;
        }
        __syncthreads();

        // ---- phase 3a: ind output + histogram (coalesced) ----
        if (tid < TILE_M) {
            int ind = sind[tid];
            out[OUT_IND + tile * TILE_M + tid] = (float)ind;
            atomicAdd(&shist[ind], 1u);
        }

        // ---- phase 3b: epilogue, WARP PER TOKEN; exact E from g_embedT (L2) ----
#pragma unroll 2
        for (int j = 0; j < 16; j++) {
            const int t   = w * 16 + j;
            const int ind = sind[t];                       // broadcast
            const size_t gt = (size_t)tile * TILE_M + t;
            float2 qv = *(const float2*)(g_embedT + ind * DIM + 2 * lane);  // coalesced L2
            float2 xv = *(const float2*)(x + gt * DIM + 2 * lane);          // coalesced
            float e0 = qv.x - xv.x, e1 = qv.y - xv.y;
            *(float2*)(out + OUT_Q + gt * DIM + 2 * lane) =
                make_float2(xv.x + e0, xv.y + e1);
            diff_acc += e0 * e0 + e1 * e1;
            atomicAdd(&g_embed_sum[ind * DIM + 2 * lane], xv.x);
            atomicAdd(&g_embed_sum[ind * DIM + 2 * lane + 1], xv.y);
        }
        __syncthreads();
    }

    // ---- diff: one double atomic per warp ----
#pragma unroll
    for (int o = 16; o; o >>= 1) diff_acc += __shfl_xor_sync(0xffffffffu, diff_acc, o);
    if (lane == 0) atomicAdd(&g_diff, (double)diff_acc);

    // ---- merge hist; last CTA finalizes + resets scratch ----
    if (tid < NE && shist[tid]) atomicAdd(&g_hist[tid], shist[tid]);
    __threadfence();
    if (tid == 0) s_rank = atomicAdd(&g_done, 1u);
    __syncthreads();

    if (s_rank == NCTA - 1) {
        const int e = tid;   // NTHR == NE == 512
        float ncs = cs_in[e] * 0.99f + 0.01f * (float)g_hist[e];
        out[OUT_CS + e] = ncs;
        ssq[e] = ncs;
        __syncthreads();
        for (int o = 256; o; o >>= 1) {
            if (e < o) ssq[e] += ssq[e + o];
            __syncthreads();
        }
        const float n   = ssq[0];
        const float csn = (ncs + 1e-5f) / (n + 0.00512f) * n;
#pragma unroll 4
        for (int d = 0; d < DIM; d++) {
            int idx = d * NE + e;
            float avg = ea_in[idx] * 0.99f + 0.01f * g_embed_sum[e * DIM + d];
            out[OUT_AVG + idx] = avg;
            out[OUT_EMB + idx] = avg / csn;
            g_embed_sum[e * DIM + d] = 0.0f;     // reset for next replay
        }
        g_hist[e] = 0u;
        if (e == 0) {
            out[OUT_DIFF] = (float)(g_diff * (1.0 / 8388608.0));
            g_diff = 0.0;
            g_done = 0u;
        }
    }
}

extern "C" void kernel_launch(void* const* d_in, const int* in_sizes, int n_in,
                              void* d_out, int out_size) {
    const float* x     = (const float*)d_in[0];
    const float* embed = (const float*)d_in[1];
    const float* cs    = (const float*)d_in[2];
    const float* ea    = (const float*)d_in[3];
    float* out = (float*)d_out;

    cudaFuncSetAttribute(vq_main, cudaFuncAttributeMaxDynamicSharedMemorySize, SMEM_TOTAL);
    vq_main<<<NCTA, NTHR, SMEM_TOTAL>>>(x, embed, cs, ea, out);
}

// round 16
// speedup vs baseline: 1.7257x; 1.7257x over previous
#include <cuda_runtime.h>
#include <cuda_fp16.h>
#include <cstdint>

#define N_TOK   131072
#define DIM     64
#define NE      512
#define TILE_M  256            // per warp-group
#define N_TILES 512
#define NTHR    1024
#define NCTA    148
#define TAU     1.3e-4f

#define OUT_Q     0ull
#define OUT_DIFF  8388608ull
#define OUT_IND   8388609ull
#define OUT_EMB   8519681ull
#define OUT_CS    8552449ull
#define OUT_AVG   8552961ull

// smem (byte offsets)
#define SB_HI   0               // f16(-2E) hi, 512 x 128B, SW128
#define SB_LO   65536           // f16 lo of (-2E)
#define SA0     131072          // A tile group 0: 256 x 128B
#define SA1     163840          // A tile group 1
#define SSQ     196608          // ||E||^2 [512]
#define SSQO    198656          // ||E||^2 + 0.5 [512+16]
#define SIND    200768          // argmin [2][256]
#define SLIST   202816          // flagged [2][256]
#define SHIST   204864          // [512]
#define SCNT    206912          // [2]
#define SMEM_TOTAL 206928

#define SWZ(o) ((o) ^ (((o) >> 3) & 0x70))

__device__ float        g_embed_sum[NE * DIM];   // [e][d]
__device__ unsigned int g_hist[NE];
__device__ double       g_diff;
__device__ unsigned int g_done;

static __device__ __forceinline__ uint32_t smem_u32(const void* p) {
    uint32_t a;
    asm("{ .reg .u64 t; cvta.to.shared.u64 t, %1; cvt.u32.u64 %0, t; }" : "=r"(a) : "l"(p));
    return a;
}
static __device__ __forceinline__ uint32_t h2u(__half2 v) {
    uint32_t u; memcpy(&u, &v, 4); return u;
}
static __device__ __forceinline__ float2 u2f2(uint32_t u) {
    __half2 h; memcpy(&h, &u, 4); return __half22float2(h);
}
static __device__ __forceinline__ void mma16816(float* c, const uint32_t* a,
                                                const uint32_t* b) {
    asm volatile(
        "mma.sync.aligned.m16n8k16.row.col.f32.f16.f16.f32 "
        "{%0,%1,%2,%3}, {%4,%5,%6,%7}, {%8,%9}, {%0,%1,%2,%3};"
        : "+f"(c[0]), "+f"(c[1]), "+f"(c[2]), "+f"(c[3])
        : "r"(a[0]), "r"(a[1]), "r"(a[2]), "r"(a[3]), "r"(b[0]), "r"(b[1]));
}
static __device__ __forceinline__ void ldsm4(uint32_t* r, uint32_t addr) {
    asm volatile("ldmatrix.sync.aligned.m8n8.x4.shared.b16 {%0,%1,%2,%3}, [%4];"
                 : "=r"(r[0]), "=r"(r[1]), "=r"(r[2]), "=r"(r[3]) : "r"(addr));
}
static __device__ __forceinline__ void top2(uint32_t& k1, uint32_t& k2, uint32_t k) {
    uint32_t mx = k > k1 ? k : k1;
    k1 = k < k1 ? k : k1;
    k2 = mx < k2 ? mx : k2;
}
#define GBAR(g) asm volatile("bar.sync %0, %1;" :: "r"((g) + 1), "r"(512) : "memory")

__global__ __launch_bounds__(NTHR, 1)
void vq_main(const float* __restrict__ x, const float* __restrict__ embed,
             const float* __restrict__ cs_in, const float* __restrict__ ea_in,
             float* __restrict__ out) {
    extern __shared__ char smc[];
    float*        ssq   = (float*)(smc + SSQ);
    float*        ssqo  = (float*)(smc + SSQO);
    unsigned int* shist = (unsigned int*)(smc + SHIST);
    int*          scnt  = (int*)(smc + SCNT);
    __shared__ unsigned int s_rank;

    const int tid  = threadIdx.x;
    const int lane = tid & 31;
    const int w    = tid >> 5;
    const int g    = tid >> 9;          // warp-group 0/1
    const int tg   = tid & 511;         // thread within group
    const int wg   = w & 15;            // warp within group
    const uint32_t sbase = smem_u32(smc);

    int*       sind  = (int*)(smc + SIND)  + g * 256;
    int*       slist = (int*)(smc + SLIST) + g * 256;
    const uint32_t SAg = (g == 0) ? SA0 : SA1;

    // ---- prologue (whole CTA) ----
    if (tid < NE) shist[tid] = 0u;
    for (int idx = tid; idx < DIM * NE; idx += NTHR) {
        int d = idx >> 9;
        int e = idx & (NE - 1);
        float v2 = -2.0f * embed[idx];
        __half h = __float2half_rn(v2);
        __half l = __float2half_rn(v2 - __half2float(h));
        uint32_t so = SWZ((uint32_t)(e * 128 + d * 2));
        *(__half*)(smc + SB_HI + so) = h;
        *(__half*)(smc + SB_LO + so) = l;
    }
    if (tid < NE) {
        float s = 0.0f;
#pragma unroll
        for (int d = 0; d < DIM; d++) {
            float v = embed[d * NE + tid];
            s = __fmaf_rn(v, v, s);
        }
        ssq[tid]  = s;
        ssqo[tid] = s + 0.5f;
    }
    if (tid < 16) ssqo[NE + tid] = 0.0f;
    __syncthreads();

    const int mat  = lane >> 3;
    const int mrow = lane & 7;
    const int q    = lane >> 2;
    const int cq   = lane & 3;
    const int tok2 = lane >> 4;
    const int fidx = lane & 15;

    float diff_acc = 0.0f;

    // group-independent tile loop (equal trip count for both groups)
    for (int tile = blockIdx.x * 2 + g; tile < N_TILES; tile += NCTA * 2) {
        // ---- phase 1: coalesced f16 convert (group-local) ----
        if (tg == 0) scnt[g] = 0;
#pragma unroll
        for (int j = 0; j < 8; j++) {
            const int t = wg * 16 + j * 2 + tok2;
            float4 v = *(const float4*)(x + ((size_t)tile * TILE_M + t) * DIM
                                        + fidx * 4);
            uint32_t pa = h2u(__float22half2_rn(make_float2(v.x, v.y)));
            uint32_t pb = h2u(__float22half2_rn(make_float2(v.z, v.w)));
            uint32_t so = SWZ((uint32_t)(t * 128 + fidx * 8));
            *(uint2*)(smc + SAg + so) = make_uint2(pa, pb);
        }
        GBAR(g);

        // ---- phase 2: warp wg owns tokens [wg*16, wg*16+16) ----
        uint32_t AH[4][4];
#pragma unroll
        for (int ks = 0; ks < 4; ks++) {
            int trow = wg * 16 + (mat & 1) * 8 + mrow;
            uint32_t off = SWZ((uint32_t)(trow * 128 + ks * 32 + (mat >> 1) * 16));
            ldsm4(AH[ks], sbase + SAg + off);
        }
        uint32_t bAddr0, bAddr1, bAddr2, bAddr3;
        {
            const uint32_t bb = (uint32_t)(((mat >> 1) * 8 + mrow) * 128 + (mat & 1) * 16);
            bAddr0 = sbase + SB_HI + SWZ(bb);
            bAddr1 = sbase + SB_HI + SWZ(bb + 32);
            bAddr2 = sbase + SB_HI + SWZ(bb + 64);
            bAddr3 = sbase + SB_HI + SWZ(bb + 96);
        }
        uint32_t k1a[2] = {~0u, ~0u}, k2a[2] = {~0u, ~0u};
        uint32_t k1b[2] = {~0u, ~0u}, k2b[2] = {~0u, ~0u};

        float2 sqa = *(const float2*)(ssqo + 2 * cq);
        float2 sqb = *(const float2*)(ssqo + 8 + 2 * cq);

#pragma unroll 1
        for (int nb = 0; nb < NE; nb += 16) {
            uint32_t BH[4][4];
            ldsm4(BH[0], bAddr0); bAddr0 += 2048;
            ldsm4(BH[1], bAddr1); bAddr1 += 2048;
            ldsm4(BH[2], bAddr2); bAddr2 += 2048;
            ldsm4(BH[3], bAddr3); bAddr3 += 2048;
            float acc[2][4];
            acc[0][0] = sqa.x; acc[0][1] = sqa.y; acc[0][2] = sqa.x; acc[0][3] = sqa.y;
            acc[1][0] = sqb.x; acc[1][1] = sqb.y; acc[1][2] = sqb.x; acc[1][3] = sqb.y;
            sqa = *(const float2*)(ssqo + (nb + 16) + 2 * cq);
            sqb = *(const float2*)(ssqo + (nb + 24) + 2 * cq);
#pragma unroll
            for (int ks = 0; ks < 4; ks++) {
                mma16816(acc[0], AH[ks], &BH[ks][0]);
                mma16816(acc[1], AH[ks], &BH[ks][2]);
            }
            const uint32_t c0 = (uint32_t)(nb + 2 * cq);
#pragma unroll
            for (int hr = 0; hr < 2; hr++) {
                top2(k1a[hr], k2a[hr], (__float_as_uint(acc[0][hr * 2 + 0]) & 0xFFFFFE00u) | c0);
                top2(k1b[hr], k2b[hr], (__float_as_uint(acc[1][hr * 2 + 0]) & 0xFFFFFE00u) | (c0 + 8));
                top2(k1a[hr], k2a[hr], (__float_as_uint(acc[0][hr * 2 + 1]) & 0xFFFFFE00u) | (c0 + 1));
                top2(k1b[hr], k2b[hr], (__float_as_uint(acc[1][hr * 2 + 1]) & 0xFFFFFE00u) | (c0 + 9));
            }
        }
#pragma unroll
        for (int r = 0; r < 2; r++) {
            uint32_t mx = k1a[r] > k1b[r] ? k1a[r] : k1b[r];
            uint32_t b1 = k1a[r] < k1b[r] ? k1a[r] : k1b[r];
            uint32_t b2 = k2a[r] < k2b[r] ? k2a[r] : k2b[r];
            b2 = mx < b2 ? mx : b2;
#pragma unroll
            for (int off = 1; off < 4; off <<= 1) {
                uint32_t o1 = __shfl_xor_sync(0xffffffffu, b1, off);
                uint32_t o2 = __shfl_xor_sync(0xffffffffu, b2, off);
                uint32_t m2 = b1 > o1 ? b1 : o1;
                b1 = b1 < o1 ? b1 : o1;
                b2 = b2 < o2 ? b2 : o2;
                b2 = m2 < b2 ? m2 : b2;
            }
            if (cq == 0) {
                int t = wg * 16 + q + r * 8;
                sind[t] = (int)(b1 & 0x1FFu);
                float f1 = __uint_as_float(b1 & 0xFFFFFE00u);
                float f2 = __uint_as_float(b2 & 0xFFFFFE00u);
                if (f2 - f1 < TAU) {
                    int idx = atomicAdd(&scnt[g], 1);
                    slist[idx] = t;
                }
            }
        }
        GBAR(g);

        // ---- phase 2b: exact fp32 rescore ----
        const int cnt = scnt[g];
        for (int i = wg; i < cnt; i += 16) {
            const int t = slist[i];
            const float* xp = x + ((size_t)tile * TILE_M + t) * DIM;
            float pf = __fmaf_rn(xp[lane], xp[lane], xp[lane + 32] * xp[lane + 32]);
#pragma unroll
            for (int off = 16; off; off >>= 1)
                pf += __shfl_xor_sync(0xffffffffu, pf, off);
            const float sumf = pf;
            float bb = 3.4028235e38f;
            int   be = 0;
#pragma unroll 1
            for (int gg = 0; gg < 16; gg++) {
                int e = gg * 32 + lane;
                float d0 = 0.f, d1 = 0.f, d2 = 0.f, d3 = 0.f;
#pragma unroll
                for (int d = 0; d < DIM; d += 4) {
                    d0 = __fmaf_rn(xp[d],     embed[d * NE + e],       d0);
                    d1 = __fmaf_rn(xp[d + 1], embed[(d + 1) * NE + e], d1);
                    d2 = __fmaf_rn(xp[d + 2], embed[(d + 2) * NE + e], d2);
                    d3 = __fmaf_rn(xp[d + 3], embed[(d + 3) * NE + e], d3);
                }
                float dot = (d0 + d1) + (d2 + d3);
                float dist = __fmaf_rn(-2.0f, dot, sumf) + ssq[e];
                if (dist < bb) { bb = dist; be = e; }
            }
#pragma unroll
            for (int off = 16; off; off >>= 1) {
                float ob = __shfl_xor_sync(0xffffffffu, bb, off);
                int   oe = __shfl_xor_sync(0xffffffffu, be, off);
                if (ob < bb || (ob == bb && oe < be)) { bb = ob; be = oe; }
            }
            if (lane == 0) sind[t] = be;
        }
        GBAR(g);

        // ---- phase 3a: ind output + histogram ----
        if (tg < TILE_M) {
            int ind = sind[tg];
            out[OUT_IND + tile * TILE_M + tg] = (float)ind;
            atomicAdd(&shist[ind], 1u);
        }

        // ---- phase 3b: epilogue, WARP PER TOKEN ----
#pragma unroll 2
        for (int j = 0; j < 16; j++) {
            const int t   = wg * 16 + j;
            const int ind = sind[t];
            const size_t gt = (size_t)tile * TILE_M + t;
            uint32_t so = SWZ((uint32_t)(ind * 128 + lane * 4));
            float2 h = u2f2(*(const uint32_t*)(smc + SB_HI + so));
            float2 l = u2f2(*(const uint32_t*)(smc + SB_LO + so));
            float q0 = -0.5f * (h.x + l.x), q1 = -0.5f * (h.y + l.y);  // exact E
            float2 xv = *(const float2*)(x + gt * DIM + 2 * lane);
            float e0 = q0 - xv.x, e1 = q1 - xv.y;
            *(float2*)(out + OUT_Q + gt * DIM + 2 * lane) =
                make_float2(xv.x + e0, xv.y + e1);
            diff_acc += e0 * e0 + e1 * e1;
            atomicAdd(&g_embed_sum[ind * DIM + 2 * lane], xv.x);
            atomicAdd(&g_embed_sum[ind * DIM + 2 * lane + 1], xv.y);
        }
        GBAR(g);
    }

    // ---- diff: one double atomic per warp ----
#pragma unroll
    for (int o = 16; o; o >>= 1) diff_acc += __shfl_xor_sync(0xffffffffu, diff_acc, o);
    if (lane == 0) atomicAdd(&g_diff, (double)diff_acc);

    // ---- merge hist; last CTA finalizes + resets scratch ----
    __syncthreads();           // both groups done (equal trip counts)
    if (tid < NE && shist[tid]) atomicAdd(&g_hist[tid], shist[tid]);
    __threadfence();
    if (tid == 0) s_rank = atomicAdd(&g_done, 1u);
    __syncthreads();

    if (s_rank == NCTA - 1) {
        const int e = tid;
        float ncs = 0.0f;
        if (e < NE) {
            ncs = cs_in[e] * 0.99f + 0.01f * (float)g_hist[e];
            out[OUT_CS + e] = ncs;
            ssq[e] = ncs;
        }
        __syncthreads();
        for (int o = 256; o; o >>= 1) {
            if (e < o && e + o < NE) ssq[e] += ssq[e + o];
            __syncthreads();
        }
        if (e < NE) {
            const float n   = ssq[0];
            const float csn = (ncs + 1e-5f) / (n + 0.00512f) * n;
#pragma unroll 4
            for (int d = 0; d < DIM; d++) {
                int idx = d * NE + e;
                float avg = ea_in[idx] * 0.99f + 0.01f * g_embed_sum[e * DIM + d];
                out[OUT_AVG + idx] = avg;
                out[OUT_EMB + idx] = avg / csn;
                g_embed_sum[e * DIM + d] = 0.0f;
            }
            g_hist[e] = 0u;
            if (e == 0) {
                out[OUT_DIFF] = (float)(g_diff * (1.0 / 8388608.0));
                g_diff = 0.0;
                g_done = 0u;
            }
        }
    }
}

extern "C" void kernel_launch(void* const* d_in, const int* in_sizes, int n_in,
                              void* d_out, int out_size) {
    const float* x     = (const float*)d_in[0];
    const float* embed = (const float*)d_in[1];
    const float* cs    = (const float*)d_in[2];
    const float* ea    = (const float*)d_in[3];
    float* out = (float*)d_out;

    cudaFuncSetAttribute(vq_main, cudaFuncAttributeMaxDynamicSharedMemorySize, SMEM_TOTAL);
    vq_main<<<NCTA, NTHR, SMEM_TOTAL>>>(x, embed, cs, ea, out);
}

// round 17
// speedup vs baseline: 1.8527x; 1.0736x over previous
#include <cuda_runtime.h>
#include <cuda_fp16.h>
#include <cstdint>

#define N_TOK   131072
#define DIM     64
#define NE      512
#define NTASK   8192            // 16-token groups
#define NTHR    1024
#define NCTA    148
#define TAU     1.3e-4f

#define OUT_Q     0ull
#define OUT_DIFF  8388608ull
#define OUT_IND   8388609ull
#define OUT_EMB   8519681ull
#define OUT_CS    8552449ull
#define OUT_AVG   8552961ull

// smem (byte offsets)
#define SB_HI   0               // f16(-2E) hi, 512 x 128B, SW128
#define SB_LO   65536           // f16 lo of (-2E)
#define SSQ     131072          // ||E||^2 [512]
#define SSQO    133120          // ||E||^2 + 0.5 [512+16]
#define SHIST   135232          // [512]
#define SMEM_TOTAL 137280

#define SWZ(o) ((o) ^ (((o) >> 3) & 0x70))

__device__ float        g_embed_sum[NE * DIM];   // [e][d]
__device__ unsigned int g_hist[NE];
__device__ double       g_diff;
__device__ unsigned int g_done;
__device__ unsigned int g_ticket;                // reset by finalizer

static __device__ __forceinline__ uint32_t smem_u32(const void* p) {
    uint32_t a;
    asm("{ .reg .u64 t; cvta.to.shared.u64 t, %1; cvt.u32.u64 %0, t; }" : "=r"(a) : "l"(p));
    return a;
}
static __device__ __forceinline__ uint32_t h2u(__half2 v) {
    uint32_t u; memcpy(&u, &v, 4); return u;
}
static __device__ __forceinline__ float2 u2f2(uint32_t u) {
    __half2 h; memcpy(&h, &u, 4); return __half22float2(h);
}
static __device__ __forceinline__ uint32_t cvt2(float2 v) {
    return h2u(__float22half2_rn(v));
}
static __device__ __forceinline__ void mma16816(float* c, const uint32_t* a,
                                                const uint32_t* b) {
    asm volatile(
        "mma.sync.aligned.m16n8k16.row.col.f32.f16.f16.f32 "
        "{%0,%1,%2,%3}, {%4,%5,%6,%7}, {%8,%9}, {%0,%1,%2,%3};"
        : "+f"(c[0]), "+f"(c[1]), "+f"(c[2]), "+f"(c[3])
        : "r"(a[0]), "r"(a[1]), "r"(a[2]), "r"(a[3]), "r"(b[0]), "r"(b[1]));
}
static __device__ __forceinline__ void ldsm4(uint32_t* r, uint32_t addr) {
    asm volatile("ldmatrix.sync.aligned.m8n8.x4.shared.b16 {%0,%1,%2,%3}, [%4];"
                 : "=r"(r[0]), "=r"(r[1]), "=r"(r[2]), "=r"(r[3]) : "r"(addr));
}
static __device__ __forceinline__ void top2(uint32_t& k1, uint32_t& k2, uint32_t k) {
    uint32_t mx = k > k1 ? k : k1;
    k1 = k < k1 ? k : k1;
    k2 = mx < k2 ? mx : k2;
}

__global__ __launch_bounds__(NTHR, 1)
void vq_main(const float* __restrict__ x, const float* __restrict__ embed,
             const float* __restrict__ cs_in, const float* __restrict__ ea_in,
             float* __restrict__ out) {
    extern __shared__ char smc[];
    float*        ssq   = (float*)(smc + SSQ);
    float*        ssqo  = (float*)(smc + SSQO);
    unsigned int* shist = (unsigned int*)(smc + SHIST);
    __shared__ unsigned int s_rank;

    const int tid  = threadIdx.x;
    const int lane = tid & 31;
    const uint32_t sbase = smem_u32(smc);

    // ---- prologue: f16 hi/lo of (-2E) + exact ||E||^2 (once per CTA) ----
    if (tid < NE) shist[tid] = 0u;
    for (int idx = tid; idx < DIM * NE; idx += NTHR) {
        int d = idx >> 9;
        int e = idx & (NE - 1);
        float v2 = -2.0f * embed[idx];
        __half h = __float2half_rn(v2);
        __half l = __float2half_rn(v2 - __half2float(h));
        uint32_t so = SWZ((uint32_t)(e * 128 + d * 2));
        *(__half*)(smc + SB_HI + so) = h;
        *(__half*)(smc + SB_LO + so) = l;
    }
    if (tid < NE) {
        float s = 0.0f;
#pragma unroll
        for (int d = 0; d < DIM; d++) {
            float v = embed[d * NE + tid];
            s = __fmaf_rn(v, v, s);
        }
        ssq[tid]  = s;
        ssqo[tid] = s + 0.5f;
    }
    if (tid < 16) ssqo[NE + tid] = 0.0f;
    __syncthreads();

    const int q  = lane >> 2;
    const int cq = lane & 3;

    // constant hoisted swizzled B base addresses (per warp-lane role)
    uint32_t bBase0, bBase1, bBase2, bBase3;
    {
        const int mat  = lane >> 3;
        const int mrow = lane & 7;
        const uint32_t bb = (uint32_t)(((mat >> 1) * 8 + mrow) * 128 + (mat & 1) * 16);
        bBase0 = sbase + SB_HI + SWZ(bb);
        bBase1 = sbase + SB_HI + SWZ(bb + 32);
        bBase2 = sbase + SB_HI + SWZ(bb + 64);
        bBase3 = sbase + SB_HI + SWZ(bb + 96);
    }

    float diff_acc = 0.0f;

    // ---- warp-autonomous task loop ----
    for (;;) {
        unsigned int task;
        if (lane == 0) task = atomicAdd(&g_ticket, 1u);
        task = __shfl_sync(0xffffffffu, task, 0);
        if (task >= NTASK) break;
        const size_t tbase = (size_t)task * 16;    // first token of group

        // ---- A fragments directly from gmem (m16n8k16 layout, registers) ----
        uint32_t AH[4][4];
        {
            const float* rA = x + (tbase + q) * DIM;
            const float* rB = rA + 8 * DIM;
#pragma unroll
            for (int ks = 0; ks < 4; ks++) {
                const int o1 = ks * 16 + 2 * cq;
                AH[ks][0] = cvt2(*(const float2*)(rA + o1));
                AH[ks][1] = cvt2(*(const float2*)(rB + o1));
                AH[ks][2] = cvt2(*(const float2*)(rA + o1 + 8));
                AH[ks][3] = cvt2(*(const float2*)(rB + o1 + 8));
            }
        }

        // ---- scan: seeded MMA, top-2 keys ----
        uint32_t bAddr0 = bBase0, bAddr1 = bBase1, bAddr2 = bBase2, bAddr3 = bBase3;
        uint32_t k1a[2] = {~0u, ~0u}, k2a[2] = {~0u, ~0u};
        uint32_t k1b[2] = {~0u, ~0u}, k2b[2] = {~0u, ~0u};
        float2 sqa = *(const float2*)(ssqo + 2 * cq);
        float2 sqb = *(const float2*)(ssqo + 8 + 2 * cq);

#pragma unroll 1
        for (int nb = 0; nb < NE; nb += 16) {
            uint32_t BH[4][4];
            ldsm4(BH[0], bAddr0); bAddr0 += 2048;
            ldsm4(BH[1], bAddr1); bAddr1 += 2048;
            ldsm4(BH[2], bAddr2); bAddr2 += 2048;
            ldsm4(BH[3], bAddr3); bAddr3 += 2048;
            float acc[2][4];
            acc[0][0] = sqa.x; acc[0][1] = sqa.y; acc[0][2] = sqa.x; acc[0][3] = sqa.y;
            acc[1][0] = sqb.x; acc[1][1] = sqb.y; acc[1][2] = sqb.x; acc[1][3] = sqb.y;
            sqa = *(const float2*)(ssqo + (nb + 16) + 2 * cq);
            sqb = *(const float2*)(ssqo + (nb + 24) + 2 * cq);
#pragma unroll
            for (int ks = 0; ks < 4; ks++) {
                mma16816(acc[0], AH[ks], &BH[ks][0]);
                mma16816(acc[1], AH[ks], &BH[ks][2]);
            }
            const uint32_t c0 = (uint32_t)(nb + 2 * cq);
#pragma unroll
            for (int hr = 0; hr < 2; hr++) {
                top2(k1a[hr], k2a[hr], (__float_as_uint(acc[0][hr * 2 + 0]) & 0xFFFFFE00u) | c0);
                top2(k1b[hr], k2b[hr], (__float_as_uint(acc[1][hr * 2 + 0]) & 0xFFFFFE00u) | (c0 + 8));
                top2(k1a[hr], k2a[hr], (__float_as_uint(acc[0][hr * 2 + 1]) & 0xFFFFFE00u) | (c0 + 1));
                top2(k1b[hr], k2b[hr], (__float_as_uint(acc[1][hr * 2 + 1]) & 0xFFFFFE00u) | (c0 + 9));
            }
        }

        // ---- merge keys; sind in registers; flags via ballot ----
        int sind_reg[2];
        uint32_t fmask[2];
#pragma unroll
        for (int r = 0; r < 2; r++) {
            uint32_t mx = k1a[r] > k1b[r] ? k1a[r] : k1b[r];
            uint32_t b1 = k1a[r] < k1b[r] ? k1a[r] : k1b[r];
            uint32_t b2 = k2a[r] < k2b[r] ? k2a[r] : k2b[r];
            b2 = mx < b2 ? mx : b2;
#pragma unroll
            for (int off = 1; off < 4; off <<= 1) {
                uint32_t o1 = __shfl_xor_sync(0xffffffffu, b1, off);
                uint32_t o2 = __shfl_xor_sync(0xffffffffu, b2, off);
                uint32_t m2 = b1 > o1 ? b1 : o1;
                b1 = b1 < o1 ? b1 : o1;
                b2 = b2 < o2 ? b2 : o2;
                b2 = m2 < b2 ? m2 : b2;
            }
            sind_reg[r] = (int)(b1 & 0x1FFu);
            float f1 = __uint_as_float(b1 & 0xFFFFFE00u);
            float f2 = __uint_as_float(b2 & 0xFFFFFE00u);
            fmask[r] = __ballot_sync(0xffffffffu, cq == 0 && (f2 - f1 < TAU));
        }

        // ---- warp-local exact rescore of flagged tokens ----
#pragma unroll
        for (int r = 0; r < 2; r++) {
            uint32_t m = fmask[r];
            while (m) {
                const int lp = __ffs(m) - 1;       // lane 4*q of flagged token
                m &= m - 1;
                const int tq = lp >> 2;
                const float* xp = x + (tbase + tq + 8 * r) * DIM;
                float pf = __fmaf_rn(xp[lane], xp[lane], xp[lane + 32] * xp[lane + 32]);
#pragma unroll
                for (int off = 16; off; off >>= 1)
                    pf += __shfl_xor_sync(0xffffffffu, pf, off);
                const float sumf = pf;
                float bb = 3.4028235e38f;
                int   be = 0;
#pragma unroll 1
                for (int gg = 0; gg < 16; gg++) {
                    int e = gg * 32 + lane;
                    float d0 = 0.f, d1 = 0.f, d2 = 0.f, d3 = 0.f;
#pragma unroll
                    for (int d = 0; d < DIM; d += 4) {
                        d0 = __fmaf_rn(xp[d],     embed[d * NE + e],       d0);
                        d1 = __fmaf_rn(xp[d + 1], embed[(d + 1) * NE + e], d1);
                        d2 = __fmaf_rn(xp[d + 2], embed[(d + 2) * NE + e], d2);
                        d3 = __fmaf_rn(xp[d + 3], embed[(d + 3) * NE + e], d3);
                    }
                    float dot = (d0 + d1) + (d2 + d3);
                    float dist = __fmaf_rn(-2.0f, dot, sumf) + ssq[e];
                    if (dist < bb) { bb = dist; be = e; }
                }
#pragma unroll
                for (int off = 16; off; off >>= 1) {
                    float ob = __shfl_xor_sync(0xffffffffu, bb, off);
                    int   oe = __shfl_xor_sync(0xffffffffu, be, off);
                    if (ob < bb || (ob == bb && oe < be)) { bb = ob; be = oe; }
                }
                be = __shfl_sync(0xffffffffu, be, 0);
                if (lane == lp) sind_reg[r] = be;
            }
        }

        // ---- ind output + histogram (lanes 4q, coalesced 4B run) ----
#pragma unroll
        for (int r = 0; r < 2; r++) {
            if (cq == 0) {
                out[OUT_IND + tbase + q + 8 * r] = (float)sind_reg[r];
                atomicAdd(&shist[sind_reg[r]], 1u);
            }
        }

        // ---- epilogue: warp per token (lane = dim pair), ind via shfl ----
#pragma unroll 2
        for (int j = 0; j < 16; j++) {
            const int ind = __shfl_sync(0xffffffffu, sind_reg[j >> 3], (j & 7) * 4);
            const size_t gt = tbase + j;
            uint32_t so = SWZ((uint32_t)(ind * 128 + lane * 4));
            float2 h = u2f2(*(const uint32_t*)(smc + SB_HI + so));
            float2 l = u2f2(*(const uint32_t*)(smc + SB_LO + so));
            float q0 = -0.5f * (h.x + l.x), q1 = -0.5f * (h.y + l.y);  // exact E
            float2 xv = *(const float2*)(x + gt * DIM + 2 * lane);
            float e0 = q0 - xv.x, e1 = q1 - xv.y;
            *(float2*)(out + OUT_Q + gt * DIM + 2 * lane) =
                make_float2(xv.x + e0, xv.y + e1);
            diff_acc += e0 * e0 + e1 * e1;
            atomicAdd(&g_embed_sum[ind * DIM + 2 * lane], xv.x);
            atomicAdd(&g_embed_sum[ind * DIM + 2 * lane + 1], xv.y);
        }
    }

    // ---- diff: one double atomic per warp ----
#pragma unroll
    for (int o = 16; o; o >>= 1) diff_acc += __shfl_xor_sync(0xffffffffu, diff_acc, o);
    if (lane == 0) atomicAdd(&g_diff, (double)diff_acc);

    // ---- merge hist; last CTA finalizes + resets scratch ----
    __syncthreads();
    if (tid < NE && shist[tid]) atomicAdd(&g_hist[tid], shist[tid]);
    __threadfence();
    if (tid == 0) s_rank = atomicAdd(&g_done, 1u);
    __syncthreads();

    if (s_rank == NCTA - 1) {
        const int e = tid;
        float ncs = 0.0f;
        if (e < NE) {
            ncs = cs_in[e] * 0.99f + 0.01f * (float)g_hist[e];
            out[OUT_CS + e] = ncs;
            ssq[e] = ncs;
        }
        __syncthreads();
        for (int o = 256; o; o >>= 1) {
            if (e < o && e + o < NE) ssq[e] += ssq[e + o];
            __syncthreads();
        }
        if (e < NE) {
            const float n   = ssq[0];
            const float csn = (ncs + 1e-5f) / (n + 0.00512f) * n;
#pragma unroll 4
            for (int d = 0; d < DIM; d++) {
                int idx = d * NE + e;
                float avg = ea_in[idx] * 0.99f + 0.01f * g_embed_sum[e * DIM + d];
                out[OUT_AVG + idx] = avg;
                out[OUT_EMB + idx] = avg / csn;
                g_embed_sum[e * DIM + d] = 0.0f;
            }
            g_hist[e] = 0u;
            if (e == 0) {
                out[OUT_DIFF] = (float)(g_diff * (1.0 / 8388608.0));
                g_diff = 0.0;
                g_done = 0u;
                g_ticket = 0u;     // reset for next graph replay
            }
        }
    }
}

extern "C" void kernel_launch(void* const* d_in, const int* in_sizes, int n_in,
                              void* d_out, int out_size) {
    const float* x     = (const float*)d_in[0];
    const float* embed = (const float*)d_in[1];
    const float* cs    = (const float*)d_in[2];
    const float* ea    = (const float*)d_in[3];
    float* out = (float*)d_out;

    cudaFuncSetAttribute(vq_main, cudaFuncAttributeMaxDynamicSharedMemorySize, SMEM_TOTAL);
    vq_main<<<NCTA, NTHR, SMEM_TOTAL>>>(x, embed, cs, ea, out);
}